// round 3
// baseline (speedup 1.0000x reference)
#include <cuda_runtime.h>
#include <cuda_bf16.h>
#include <math.h>

// Problem constants
#define N_TOK 16384
#define D_IN  1024
#define D_OUT 1024
#define N_EXP 8
#define RANK  16
#define TOPK  2
#define SCALING (32.0f / 16.0f)   // ALPHA / R = 2.0

// Scratch: per-token gated+scaled low-rank activations and expert ids.
// hh[n][k*16+r] = SCALING * weight_k * sum_d tokens[n][d] * A[e_k][d][r]
__device__ float g_hh[(size_t)N_TOK * 32];
__device__ int   g_eid[(size_t)N_TOK * 2];

// ---------------------------------------------------------------------------
// Kernel 1: router (logits, top-2, softmax) + low-rank h for selected experts
// One block per token, 256 threads (8 warps).
// ---------------------------------------------------------------------------
__global__ __launch_bounds__(256) void router_h_kernel(
    const float* __restrict__ tokens,   // [N, D_IN]
    const float* __restrict__ A,        // [E, D_IN, R]
    const float* __restrict__ Wg,       // [D_IN, E]
    float* __restrict__ out_logits,     // [N, E]
    float* __restrict__ out_sel,        // [N, K] (as float)
    float* __restrict__ out_wts)        // [N, K]
{
    const int n    = blockIdx.x;
    const int tid  = threadIdx.x;
    const int w    = tid >> 5;
    const int lane = tid & 31;

    __shared__ float t_s[D_IN];
    __shared__ float logits_s[N_EXP];
    __shared__ float part_s[8][16];
    __shared__ int   eid_s[2];
    __shared__ float scale_s[2];

    const float* trow = tokens + (size_t)n * D_IN;
    for (int i = tid; i < D_IN; i += 256) t_s[i] = trow[i];
    __syncthreads();

    // --- Phase 1: logits. Warp w computes logit for expert w. ---
    float acc = 0.f;
    for (int d = lane; d < D_IN; d += 32)
        acc += t_s[d] * Wg[d * N_EXP + w];
    #pragma unroll
    for (int off = 16; off; off >>= 1)
        acc += __shfl_xor_sync(0xffffffffu, acc, off);
    if (lane == 0) logits_s[w] = acc;
    __syncthreads();

    // --- Phase 2: top-2 + softmax (thread 0), write router outputs ---
    if (tid == 0) {
        int i0 = 0; float v0 = logits_s[0];
        #pragma unroll
        for (int e = 1; e < N_EXP; e++)
            if (logits_s[e] > v0) { v0 = logits_s[e]; i0 = e; }
        int i1 = -1; float v1 = -INFINITY;
        #pragma unroll
        for (int e = 0; e < N_EXP; e++)
            if (e != i0 && logits_s[e] > v1) { v1 = logits_s[e]; i1 = e; }
        float e1v   = __expf(v1 - v0);
        float denom = 1.0f + e1v;
        float p0 = 1.0f / denom;
        float p1 = e1v / denom;
        out_sel[(size_t)n * TOPK + 0] = (float)i0;
        out_sel[(size_t)n * TOPK + 1] = (float)i1;
        out_wts[(size_t)n * TOPK + 0] = p0;
        out_wts[(size_t)n * TOPK + 1] = p1;
        eid_s[0]   = i0;       eid_s[1]   = i1;
        scale_s[0] = SCALING * p0;
        scale_s[1] = SCALING * p1;
        g_eid[(size_t)n * 2 + 0] = i0;
        g_eid[(size_t)n * 2 + 1] = i1;
    }
    if (tid < N_EXP) out_logits[(size_t)n * N_EXP + tid] = logits_s[tid];
    __syncthreads();

    // --- Phase 3: h[k][r] = sum_d t[d] * A[e_k][d][r] for 2 selected experts
    // Warps 0-3 -> expert slot 0, warps 4-7 -> slot 1; each warp a 256-d slice.
    const int k = w >> 2;
    const int q = w & 3;
    const int e = eid_s[k];
    const float* Abase = A + (size_t)e * D_IN * RANK;

    float a16[16];
    #pragma unroll
    for (int r = 0; r < 16; r++) a16[r] = 0.f;

    #pragma unroll
    for (int it = 0; it < 8; it++) {
        int d = q * 256 + it * 32 + lane;
        float tv = t_s[d];
        const float4* ap = (const float4*)(Abase + (size_t)d * RANK);
        float4 a0 = ap[0], a1 = ap[1], a2 = ap[2], a3 = ap[3];
        a16[0]  += tv * a0.x;  a16[1]  += tv * a0.y;
        a16[2]  += tv * a0.z;  a16[3]  += tv * a0.w;
        a16[4]  += tv * a1.x;  a16[5]  += tv * a1.y;
        a16[6]  += tv * a1.z;  a16[7]  += tv * a1.w;
        a16[8]  += tv * a2.x;  a16[9]  += tv * a2.y;
        a16[10] += tv * a2.z;  a16[11] += tv * a2.w;
        a16[12] += tv * a3.x;  a16[13] += tv * a3.y;
        a16[14] += tv * a3.z;  a16[15] += tv * a3.w;
    }
    // reduce 16 values across the warp
    #pragma unroll
    for (int off = 16; off; off >>= 1) {
        #pragma unroll
        for (int r = 0; r < 16; r++)
            a16[r] += __shfl_xor_sync(0xffffffffu, a16[r], off);
    }
    if (lane == 0) {
        #pragma unroll
        for (int r = 0; r < 16; r++) part_s[w][r] = a16[r];
    }
    __syncthreads();
    if (tid < 32) {
        int k2 = tid >> 4, r = tid & 15;
        float s = part_s[k2 * 4 + 0][r] + part_s[k2 * 4 + 1][r] +
                  part_s[k2 * 4 + 2][r] + part_s[k2 * 4 + 3][r];
        g_hh[(size_t)n * 32 + k2 * 16 + r] = s * scale_s[k2];
    }
}

// ---------------------------------------------------------------------------
// Kernel 2: base GEMM (tokens @ W_base) with fused LoRA epilogue.
// 128x128 tile, BK=16, 256 threads, 8x8 per-thread microtile, fp32.
// ---------------------------------------------------------------------------
#define BM 128
#define BN 128
#define BK 16

__global__ __launch_bounds__(256, 2) void gemm_lora_kernel(
    const float* __restrict__ T,      // [N, D_IN]
    const float* __restrict__ W,      // [D_IN, D_OUT]
    const float* __restrict__ Bm,     // [E, R, D_OUT]
    float* __restrict__ out)          // [N, D_OUT]
{
    __shared__ float As[BK][BM + 4];
    __shared__ float Bs[BK][BN];
    __shared__ float hh_s[BM * 32];
    __shared__ int   eid_sh[BM * 2];

    const int bm = blockIdx.y * BM;
    const int bn = blockIdx.x * BN;
    const int tid = threadIdx.x;
    const int tx = tid & 15;   // col group
    const int ty = tid >> 4;   // row group

    // stage per-row LoRA data (independent of main loop; covered by first sync)
    for (int i = tid; i < BM * 32; i += 256)
        hh_s[i] = g_hh[(size_t)bm * 32 + i];
    for (int i = tid; i < BM * 2; i += 256)
        eid_sh[i] = g_eid[(size_t)bm * 2 + i];

    float acc[8][8];
    #pragma unroll
    for (int i = 0; i < 8; i++)
        #pragma unroll
        for (int j = 0; j < 8; j++) acc[i][j] = 0.f;

    for (int k0 = 0; k0 < D_IN; k0 += BK) {
        // Load A tile (tokens), store transposed As[k][m]
        #pragma unroll
        for (int i = 0; i < 2; i++) {
            int idx = tid + i * 256;          // 0..511 float4s
            int row = idx >> 2;               // 0..127
            int c4  = idx & 3;                // 0..3
            float4 v = *(const float4*)(T + (size_t)(bm + row) * D_IN + k0 + c4 * 4);
            As[c4 * 4 + 0][row] = v.x;
            As[c4 * 4 + 1][row] = v.y;
            As[c4 * 4 + 2][row] = v.z;
            As[c4 * 4 + 3][row] = v.w;
        }
        // Load B tile (W_base) Bs[k][n]
        #pragma unroll
        for (int i = 0; i < 2; i++) {
            int idx = tid + i * 256;          // 0..511 float4s
            int row = idx >> 5;               // 0..15
            int c4  = idx & 31;               // 0..31
            *(float4*)&Bs[row][c4 * 4] =
                *(const float4*)(W + (size_t)(k0 + row) * D_OUT + bn + c4 * 4);
        }
        __syncthreads();

        #pragma unroll
        for (int kk = 0; kk < BK; kk++) {
            float ra[8], rb[8];
            *(float4*)&ra[0] = *(const float4*)&As[kk][ty * 8];
            *(float4*)&ra[4] = *(const float4*)&As[kk][ty * 8 + 4];
            *(float4*)&rb[0] = *(const float4*)&Bs[kk][tx * 8];
            *(float4*)&rb[4] = *(const float4*)&Bs[kk][tx * 8 + 4];
            #pragma unroll
            for (int i = 0; i < 8; i++)
                #pragma unroll
                for (int j = 0; j < 8; j++)
                    acc[i][j] += ra[i] * rb[j];
        }
        __syncthreads();
    }

    // ---- LoRA epilogue: acc[i][:] += sum_{j<32} hh[row][j] * B[e][r][m] ----
    const int mcol = bn + tx * 8;
    #pragma unroll
    for (int i = 0; i < 8; i++) {
        int lr = ty * 8 + i;
        int e0 = eid_sh[lr * 2 + 0];
        int e1 = eid_sh[lr * 2 + 1];
        const float* B0 = Bm + (size_t)e0 * RANK * D_OUT + mcol;
        const float* B1 = Bm + (size_t)e1 * RANK * D_OUT + mcol;
        const float* hrow = &hh_s[lr * 32];
        #pragma unroll
        for (int r = 0; r < RANK; r++) {
            float h0 = hrow[r];
            float4 b0a = *(const float4*)(B0 + (size_t)r * D_OUT);
            float4 b0b = *(const float4*)(B0 + (size_t)r * D_OUT + 4);
            acc[i][0] += h0 * b0a.x; acc[i][1] += h0 * b0a.y;
            acc[i][2] += h0 * b0a.z; acc[i][3] += h0 * b0a.w;
            acc[i][4] += h0 * b0b.x; acc[i][5] += h0 * b0b.y;
            acc[i][6] += h0 * b0b.z; acc[i][7] += h0 * b0b.w;
            float h1 = hrow[16 + r];
            float4 b1a = *(const float4*)(B1 + (size_t)r * D_OUT);
            float4 b1b = *(const float4*)(B1 + (size_t)r * D_OUT + 4);
            acc[i][0] += h1 * b1a.x; acc[i][1] += h1 * b1a.y;
            acc[i][2] += h1 * b1a.z; acc[i][3] += h1 * b1a.w;
            acc[i][4] += h1 * b1b.x; acc[i][5] += h1 * b1b.y;
            acc[i][6] += h1 * b1b.z; acc[i][7] += h1 * b1b.w;
        }
    }

    // ---- write out ----
    #pragma unroll
    for (int i = 0; i < 8; i++) {
        float* orow = out + (size_t)(bm + ty * 8 + i) * D_OUT + mcol;
        *(float4*)orow       = *(float4*)&acc[i][0];
        *(float4*)(orow + 4) = *(float4*)&acc[i][4];
    }
}

// ---------------------------------------------------------------------------
extern "C" void kernel_launch(void* const* d_in, const int* in_sizes, int n_in,
                              void* d_out, int out_size) {
    const float* tokens = (const float*)d_in[0];
    const float* W_base = (const float*)d_in[1];
    const float* A      = (const float*)d_in[2];
    const float* B      = (const float*)d_in[3];
    const float* W_gate = (const float*)d_in[4];

    float* out        = (float*)d_out;                       // [N, D_OUT]
    float* out_logits = out + (size_t)N_TOK * D_OUT;         // [N, E]
    float* out_sel    = out_logits + (size_t)N_TOK * N_EXP;  // [N, K]
    float* out_wts    = out_sel + (size_t)N_TOK * TOPK;      // [N, K]

    router_h_kernel<<<N_TOK, 256>>>(tokens, A, W_gate,
                                    out_logits, out_sel, out_wts);

    dim3 grid(D_OUT / BN, N_TOK / BM);
    gemm_lora_kernel<<<grid, 256>>>(tokens, W_base, B, out);
}

// round 5
// speedup vs baseline: 2.4844x; 2.4844x over previous
#include <cuda_runtime.h>
#include <cuda_bf16.h>
#include <math.h>
#include <stdint.h>

// ---------------- Problem constants ----------------
#define N_TOK 16384
#define D_IN  1024
#define D_OUT 1024
#define N_EXP 8
#define RANK  16
#define SCALING 2.0f   // ALPHA / R

// ---------------- Device scratch ----------------
__device__ __nv_bfloat16 g_Ah[(size_t)N_TOK * D_IN];   // tokens hi   [n][k]
__device__ __nv_bfloat16 g_Al[(size_t)N_TOK * D_IN];   // tokens lo
__device__ __nv_bfloat16 g_Wh[(size_t)D_IN * D_OUT];   // W_base hi   [k][n]
__device__ __nv_bfloat16 g_Wl[(size_t)D_IN * D_OUT];
__device__ __nv_bfloat16 g_Bc_h[D_IN * 160];           // [A_flat|Wg|0] hi [k][j]
__device__ __nv_bfloat16 g_Bc_l[D_IN * 160];
__device__ __nv_bfloat16 g_Bf_h[128 * D_OUT];          // B_flat hi   [j][m]
__device__ __nv_bfloat16 g_Bf_l[128 * D_OUT];
__device__ __nv_bfloat16 g_Hh[(size_t)N_TOK * 128];    // gated H hi  [n][j]
__device__ __nv_bfloat16 g_Hl[(size_t)N_TOK * 128];
__device__ float         g_h[(size_t)N_TOK * 160];     // GEMM1 out (h + logits)

// ---------------- PTX helpers (baseline ISA only) ----------------
__device__ __forceinline__ uint32_t s2u(const void* p) {
    uint32_t a;
    asm("{ .reg .u64 t; cvta.to.shared.u64 t, %1; cvt.u32.u64 %0, t; }"
        : "=r"(a) : "l"(p));
    return a;
}
__device__ __forceinline__ void cp16(uint32_t dst, const void* src) {
    asm volatile("cp.async.cg.shared.global [%0], [%1], 16;"
                 :: "r"(dst), "l"(__cvta_generic_to_global(src)));
}
#define CP_COMMIT() asm volatile("cp.async.commit_group;" ::: "memory")
#define CP_WAIT1()  asm volatile("cp.async.wait_group 1;" ::: "memory")

__device__ __forceinline__ void ldsm4(uint32_t* r, uint32_t a) {
    asm volatile("ldmatrix.sync.aligned.m8n8.x4.shared.b16 {%0,%1,%2,%3}, [%4];"
                 : "=r"(r[0]), "=r"(r[1]), "=r"(r[2]), "=r"(r[3]) : "r"(a));
}
__device__ __forceinline__ void ldsm4t(uint32_t* r, uint32_t a) {
    asm volatile("ldmatrix.sync.aligned.m8n8.x4.trans.shared.b16 {%0,%1,%2,%3}, [%4];"
                 : "=r"(r[0]), "=r"(r[1]), "=r"(r[2]), "=r"(r[3]) : "r"(a));
}
__device__ __forceinline__ void mma_bf16(float* c, const uint32_t* a,
                                         uint32_t b0, uint32_t b1) {
    asm volatile(
        "mma.sync.aligned.m16n8k16.row.col.f32.bf16.bf16.f32 "
        "{%0,%1,%2,%3}, {%4,%5,%6,%7}, {%8,%9}, {%0,%1,%2,%3};"
        : "+f"(c[0]), "+f"(c[1]), "+f"(c[2]), "+f"(c[3])
        : "r"(a[0]), "r"(a[1]), "r"(a[2]), "r"(a[3]), "r"(b0), "r"(b1));
}

// ---------------- Conversion helpers ----------------
__device__ __forceinline__ void split2(float v, __nv_bfloat16& h, __nv_bfloat16& l) {
    h = __float2bfloat16(v);
    l = __float2bfloat16(v - __bfloat162float(h));
}
__device__ __forceinline__ uint32_t pack2(__nv_bfloat16 a, __nv_bfloat16 b) {
    return (uint32_t)__bfloat16_as_ushort(a) | ((uint32_t)__bfloat16_as_ushort(b) << 16);
}

// tokens -> g_Ah/g_Al, vectorized
__global__ __launch_bounds__(256) void conv_tok(const float4* __restrict__ t) {
    size_t i = (size_t)blockIdx.x * 256 + threadIdx.x;   // 4M float4
    float4 v = t[i];
    __nv_bfloat16 h0, h1, h2, h3, l0, l1, l2, l3;
    split2(v.x, h0, l0); split2(v.y, h1, l1);
    split2(v.z, h2, l2); split2(v.w, h3, l3);
    ((uint2*)g_Ah)[i] = make_uint2(pack2(h0, h1), pack2(h2, h3));
    ((uint2*)g_Al)[i] = make_uint2(pack2(l0, l1), pack2(l2, l3));
}

// W_base -> g_Wh/g_Wl (same [k][n] layout, elementwise)
__global__ __launch_bounds__(256) void conv_w(const float4* __restrict__ W) {
    size_t i = (size_t)blockIdx.x * 256 + threadIdx.x;   // 256K float4
    float4 v = W[i];
    __nv_bfloat16 h0, h1, h2, h3, l0, l1, l2, l3;
    split2(v.x, h0, l0); split2(v.y, h1, l1);
    split2(v.z, h2, l2); split2(v.w, h3, l3);
    ((uint2*)g_Wh)[i] = make_uint2(pack2(h0, h1), pack2(h2, h3));
    ((uint2*)g_Wl)[i] = make_uint2(pack2(l0, l1), pack2(l2, l3));
}

// [A_flat | W_gate | 0] -> g_Bc ([d][j], j<128: A[e][d][r], 128..135: Wg[d][e])
__global__ __launch_bounds__(256) void conv_bc(const float* __restrict__ A,
                                               const float* __restrict__ Wg) {
    int i = blockIdx.x * 256 + threadIdx.x;   // 1024*160
    if (i >= 160 * 1024) return;
    int d = i / 160, j = i % 160;
    float v = 0.f;
    if (j < 128) { int e = j >> 4, r = j & 15; v = A[(size_t)e * 16384 + d * 16 + r]; }
    else if (j < 136) v = Wg[(size_t)d * 8 + (j - 128)];
    __nv_bfloat16 h, l; split2(v, h, l);
    g_Bc_h[i] = h; g_Bc_l[i] = l;
}

// B [E][R][D_OUT] -> g_Bf ([j][m], identical flattening)
__global__ __launch_bounds__(256) void conv_bf(const float4* __restrict__ B) {
    int i = blockIdx.x * 256 + threadIdx.x;   // 32K float4
    float4 v = B[i];
    __nv_bfloat16 h0, h1, h2, h3, l0, l1, l2, l3;
    split2(v.x, h0, l0); split2(v.y, h1, l1);
    split2(v.z, h2, l2); split2(v.w, h3, l3);
    ((uint2*)g_Bf_h)[i] = make_uint2(pack2(h0, h1), pack2(h2, h3));
    ((uint2*)g_Bf_l)[i] = make_uint2(pack2(l0, l1), pack2(l2, l3));
}

// ---------------- Router: top-2 softmax + dense gated H ----------------
__global__ __launch_bounds__(256) void router_k(float* __restrict__ out_logits,
                                                float* __restrict__ out_sel,
                                                float* __restrict__ out_wts) {
    int w = threadIdx.x >> 5, lane = threadIdx.x & 31;
    int n = blockIdx.x * 8 + w;
    const float* hrow = g_h + (size_t)n * 160;
    float lg = (lane < 8) ? hrow[128 + lane] : -1e30f;
    if (lane < 8) out_logits[(size_t)n * 8 + lane] = lg;
    float v0 = -1e30f; int i0 = 0;
    #pragma unroll
    for (int e = 0; e < 8; e++) {
        float v = __shfl_sync(0xffffffffu, lg, e);
        if (v > v0) { v0 = v; i0 = e; }
    }
    float v1 = -1e30f; int i1 = 0;
    #pragma unroll
    for (int e = 0; e < 8; e++) {
        float v = __shfl_sync(0xffffffffu, lg, e);
        if (e != i0 && v > v1) { v1 = v; i1 = e; }
    }
    float e1v = __expf(v1 - v0);
    float p0 = 1.0f / (1.0f + e1v);
    float p1 = e1v * p0;
    if (lane == 0) {
        out_sel[(size_t)n * 2 + 0] = (float)i0;
        out_sel[(size_t)n * 2 + 1] = (float)i1;
        out_wts[(size_t)n * 2 + 0] = p0;
        out_wts[(size_t)n * 2 + 1] = p1;
    }
    float s0 = SCALING * p0, s1 = SCALING * p1;
    int j0 = lane * 4;
    int e = lane >> 2;
    float g = (e == i0) ? s0 : ((e == i1) ? s1 : 0.f);
    float4 h4 = *(const float4*)(hrow + j0);
    __nv_bfloat16 h0, h1, h2, h3, l0, l1, l2, l3;
    split2(h4.x * g, h0, l0); split2(h4.y * g, h1, l1);
    split2(h4.z * g, h2, l2); split2(h4.w * g, h3, l3);
    *(uint2*)&g_Hh[(size_t)n * 128 + j0] = make_uint2(pack2(h0, h1), pack2(h2, h3));
    *(uint2*)&g_Hl[(size_t)n * 128 + j0] = make_uint2(pack2(l0, l1), pack2(l2, l3));
}

// ---------------- HMMA split-bf16 GEMM ----------------
// BM=128, BK=32, 8 warps as 4(m) x 2(n); warp tile 32 x (BN/2).
// WHICH=0: g_h = tokens @ Bc         (BN=160, K=3x1024)
// WHICH=1: out = tokens @ W + H @ Bf (BN=128, K=3x1024 + 3x128)
template<int BN, int WHICH>
__global__ __launch_bounds__(256) void gemm_mma(float* __restrict__ outp) {
    constexpr int BM = 128, BK = 32;
    constexpr int HN = BN / 2;       // cols per n-warp
    constexpr int N8 = HN / 8;       // n8 tiles per warp
    constexpr int NT2 = N8 / 2;      // ldsm.x4.trans per kk
    constexpr int LDA = BK + 8;      // pad: conflict-free ldmatrix
    constexpr int LDB = BN + 8;

    __shared__ __nv_bfloat16 As[2][BM][LDA];
    __shared__ __nv_bfloat16 Bs[2][BK][LDB];

    const int tid = threadIdx.x, w = tid >> 5, lane = tid & 31;
    const int wm = w & 3, wn = w >> 2;
    const int lr = lane & 15, lc8 = (lane >> 4) * 8;
    const int bm = blockIdx.y * BM;
    const int bn = blockIdx.x * BN;

    // K-segment tables (split-bf16 passes laid out along K)
    const __nv_bfloat16 *Asrc[6], *Bsrc[6];
    int astr[6], kst[7];
    int NSEG, TOT;
    if constexpr (WHICH == 0) {
        Asrc[0] = g_Ah; Asrc[1] = g_Ah; Asrc[2] = g_Al;
        Bsrc[0] = g_Bc_h; Bsrc[1] = g_Bc_l; Bsrc[2] = g_Bc_h;
        astr[0] = astr[1] = astr[2] = 1024;
        kst[0] = 0; kst[1] = 1024; kst[2] = 2048; kst[3] = 3072;
        NSEG = 3; TOT = 3072 / BK;
    } else {
        Asrc[0] = g_Ah; Asrc[1] = g_Ah; Asrc[2] = g_Al;
        Bsrc[0] = g_Wh; Bsrc[1] = g_Wl; Bsrc[2] = g_Wh;
        Asrc[3] = g_Hh; Asrc[4] = g_Hh; Asrc[5] = g_Hl;
        Bsrc[3] = g_Bf_h; Bsrc[4] = g_Bf_l; Bsrc[5] = g_Bf_h;
        astr[0] = astr[1] = astr[2] = 1024;
        astr[3] = astr[4] = astr[5] = 128;
        kst[0] = 0; kst[1] = 1024; kst[2] = 2048; kst[3] = 3072;
        kst[4] = 3200; kst[5] = 3328; kst[6] = 3456;
        NSEG = 6; TOT = 3456 / BK;
    }
    const int bstr = (WHICH == 0) ? 160 : 1024;  // B row stride (n-width)

    const uint32_t sA = s2u(&As[0][0][0]);
    const uint32_t sB = s2u(&Bs[0][0][0]);
    constexpr uint32_t ASZ = BM * LDA * 2, BSZ = BK * LDB * 2;

    auto load_tile = [&](int t, int buf) {
        int kg = t * BK, si = 0;
        while (si < NSEG - 1 && kg >= kst[si + 1]) si++;
        const __nv_bfloat16* Ap = Asrc[si] + (size_t)bm * astr[si] + (kg - kst[si]);
        const __nv_bfloat16* Bp = Bsrc[si] + (size_t)(kg - kst[si]) * bstr + bn;
        const int as = astr[si];
        const uint32_t dA = sA + buf * ASZ, dB = sB + buf * BSZ;
        #pragma unroll
        for (int i = 0; i < 2; i++) {                       // A: 128 x 32 halves
            int idx = tid + i * 256;
            int row = idx >> 2, c = idx & 3;
            cp16(dA + (row * LDA + c * 8) * 2, Ap + (size_t)row * as + c * 8);
        }
        constexpr int NBCH = BK * BN / 8;                   // B: 32 x BN halves
        #pragma unroll
        for (int i = 0; i < (NBCH + 255) / 256; i++) {
            int idx = tid + i * 256;
            if ((NBCH % 256 == 0) || idx < NBCH) {
                int row = idx / (BN / 8), c = idx % (BN / 8);
                cp16(dB + (row * LDB + c * 8) * 2, Bp + (size_t)row * bstr + c * 8);
            }
        }
    };

    float acc[2][N8][4];
    #pragma unroll
    for (int mt = 0; mt < 2; mt++)
        #pragma unroll
        for (int nt = 0; nt < N8; nt++)
            #pragma unroll
            for (int q = 0; q < 4; q++) acc[mt][nt][q] = 0.f;

    // ldmatrix base addresses (buf 0, kk 0)
    uint32_t aab[2], bab[NT2];
    #pragma unroll
    for (int mt = 0; mt < 2; mt++)
        aab[mt] = sA + ((wm * 32 + mt * 16 + lr) * LDA + lc8) * 2;
    #pragma unroll
    for (int nt2 = 0; nt2 < NT2; nt2++)
        bab[nt2] = sB + (lr * LDB + wn * HN + nt2 * 16 + lc8) * 2;

    load_tile(0, 0);
    CP_COMMIT();

    for (int t = 0; t < TOT; t++) {
        const int buf = t & 1;
        if (t + 1 < TOT) load_tile(t + 1, buf ^ 1);
        CP_COMMIT();
        CP_WAIT1();
        __syncthreads();

        #pragma unroll
        for (int kk = 0; kk < BK; kk += 16) {
            uint32_t af[2][4];
            ldsm4(af[0], aab[0] + buf * ASZ + kk * 2);
            ldsm4(af[1], aab[1] + buf * ASZ + kk * 2);
            #pragma unroll
            for (int nt2 = 0; nt2 < NT2; nt2++) {
                uint32_t bf[4];
                ldsm4t(bf, bab[nt2] + buf * BSZ + kk * LDB * 2);
                #pragma unroll
                for (int mt = 0; mt < 2; mt++) {
                    mma_bf16(acc[mt][2 * nt2],     af[mt], bf[0], bf[1]);
                    mma_bf16(acc[mt][2 * nt2 + 1], af[mt], bf[2], bf[3]);
                }
            }
        }
        __syncthreads();
    }

    // epilogue: c frag lane mapping (row = lane/4 [+8], col = 2*(lane%4))
    float* out = (WHICH == 0) ? g_h : outp;
    const int ld = (WHICH == 0) ? 160 : D_OUT;
    #pragma unroll
    for (int mt = 0; mt < 2; mt++) {
        int r0 = bm + wm * 32 + mt * 16 + (lane >> 2);
        #pragma unroll
        for (int nt = 0; nt < N8; nt++) {
            int c0 = bn + wn * HN + nt * 8 + 2 * (lane & 3);
            *(float2*)(out + (size_t)r0 * ld + c0) =
                make_float2(acc[mt][nt][0], acc[mt][nt][1]);
            *(float2*)(out + (size_t)(r0 + 8) * ld + c0) =
                make_float2(acc[mt][nt][2], acc[mt][nt][3]);
        }
    }
}

// ---------------- Launch ----------------
extern "C" void kernel_launch(void* const* d_in, const int* in_sizes, int n_in,
                              void* d_out, int out_size) {
    const float* tokens = (const float*)d_in[0];
    const float* W_base = (const float*)d_in[1];
    const float* A      = (const float*)d_in[2];
    const float* B      = (const float*)d_in[3];
    const float* W_gate = (const float*)d_in[4];

    float* out        = (float*)d_out;
    float* out_logits = out + (size_t)N_TOK * D_OUT;
    float* out_sel    = out_logits + (size_t)N_TOK * N_EXP;
    float* out_wts    = out_sel + (size_t)N_TOK * 2;

    conv_tok<<<16384, 256>>>((const float4*)tokens);
    conv_w<<<1024, 256>>>((const float4*)W_base);
    conv_bc<<<640, 256>>>(A, W_gate);
    conv_bf<<<128, 256>>>((const float4*)B);

    gemm_mma<160, 0><<<dim3(1, N_TOK / 128), 256>>>(nullptr);

    router_k<<<N_TOK / 8, 256>>>(out_logits, out_sel, out_wts);

    gemm_mma<128, 1><<<dim3(D_OUT / 128, N_TOK / 128), 256>>>(out);
}

// round 6
// speedup vs baseline: 2.7325x; 1.0999x over previous
#include <cuda_runtime.h>
#include <cuda_bf16.h>
#include <math.h>
#include <stdint.h>

// ---------------- Problem constants ----------------
#define N_TOK 16384
#define D_IN  1024
#define D_OUT 1024
#define N_EXP 8
#define RANK  16
#define SCALING 2.0f   // ALPHA / R

// ---------------- Device scratch ----------------
__device__ __nv_bfloat16 g_Ah[(size_t)N_TOK * D_IN];   // tokens hi   [n][k]
__device__ __nv_bfloat16 g_Al[(size_t)N_TOK * D_IN];   // tokens lo
__device__ __nv_bfloat16 g_Wh[(size_t)D_IN * D_OUT];   // W_base hi   [k][n]
__device__ __nv_bfloat16 g_Wl[(size_t)D_IN * D_OUT];
__device__ __nv_bfloat16 g_Bc_h[D_IN * 160];           // [A_flat|Wg|0] hi [k][j]
__device__ __nv_bfloat16 g_Bc_l[D_IN * 160];
__device__ __nv_bfloat16 g_Bf_h[128 * D_OUT];          // B_flat hi   [j][m]
__device__ __nv_bfloat16 g_Bf_l[128 * D_OUT];
__device__ __nv_bfloat16 g_Hh[(size_t)N_TOK * 128];    // gated H hi  [n][j]
__device__ __nv_bfloat16 g_Hl[(size_t)N_TOK * 128];
__device__ float         g_h[(size_t)N_TOK * 160];     // GEMM1 out (h + logits)

// ---------------- PTX helpers (baseline ISA only) ----------------
__device__ __forceinline__ uint32_t s2u(const void* p) {
    uint32_t a;
    asm("{ .reg .u64 t; cvta.to.shared.u64 t, %1; cvt.u32.u64 %0, t; }"
        : "=r"(a) : "l"(p));
    return a;
}
__device__ __forceinline__ void cp16(uint32_t dst, const void* src) {
    asm volatile("cp.async.cg.shared.global [%0], [%1], 16;"
                 :: "r"(dst), "l"(__cvta_generic_to_global(src)));
}
#define CP_COMMIT() asm volatile("cp.async.commit_group;" ::: "memory")

__device__ __forceinline__ void ldsm4(uint32_t* r, uint32_t a) {
    asm volatile("ldmatrix.sync.aligned.m8n8.x4.shared.b16 {%0,%1,%2,%3}, [%4];"
                 : "=r"(r[0]), "=r"(r[1]), "=r"(r[2]), "=r"(r[3]) : "r"(a));
}
__device__ __forceinline__ void ldsm4t(uint32_t* r, uint32_t a) {
    asm volatile("ldmatrix.sync.aligned.m8n8.x4.trans.shared.b16 {%0,%1,%2,%3}, [%4];"
                 : "=r"(r[0]), "=r"(r[1]), "=r"(r[2]), "=r"(r[3]) : "r"(a));
}
__device__ __forceinline__ void mma_bf16(float* c, const uint32_t* a,
                                         uint32_t b0, uint32_t b1) {
    asm volatile(
        "mma.sync.aligned.m16n8k16.row.col.f32.bf16.bf16.f32 "
        "{%0,%1,%2,%3}, {%4,%5,%6,%7}, {%8,%9}, {%0,%1,%2,%3};"
        : "+f"(c[0]), "+f"(c[1]), "+f"(c[2]), "+f"(c[3])
        : "r"(a[0]), "r"(a[1]), "r"(a[2]), "r"(a[3]), "r"(b0), "r"(b1));
}

// ---------------- Conversion helpers ----------------
__device__ __forceinline__ void split2(float v, __nv_bfloat16& h, __nv_bfloat16& l) {
    h = __float2bfloat16(v);
    l = __float2bfloat16(v - __bfloat162float(h));
}
__device__ __forceinline__ uint32_t pack2(__nv_bfloat16 a, __nv_bfloat16 b) {
    return (uint32_t)__bfloat16_as_ushort(a) | ((uint32_t)__bfloat16_as_ushort(b) << 16);
}

__global__ __launch_bounds__(256) void conv_tok(const float4* __restrict__ t) {
    size_t i = (size_t)blockIdx.x * 256 + threadIdx.x;   // 4M float4
    float4 v = t[i];
    __nv_bfloat16 h0, h1, h2, h3, l0, l1, l2, l3;
    split2(v.x, h0, l0); split2(v.y, h1, l1);
    split2(v.z, h2, l2); split2(v.w, h3, l3);
    ((uint2*)g_Ah)[i] = make_uint2(pack2(h0, h1), pack2(h2, h3));
    ((uint2*)g_Al)[i] = make_uint2(pack2(l0, l1), pack2(l2, l3));
}

__global__ __launch_bounds__(256) void conv_w(const float4* __restrict__ W) {
    size_t i = (size_t)blockIdx.x * 256 + threadIdx.x;   // 256K float4
    float4 v = W[i];
    __nv_bfloat16 h0, h1, h2, h3, l0, l1, l2, l3;
    split2(v.x, h0, l0); split2(v.y, h1, l1);
    split2(v.z, h2, l2); split2(v.w, h3, l3);
    ((uint2*)g_Wh)[i] = make_uint2(pack2(h0, h1), pack2(h2, h3));
    ((uint2*)g_Wl)[i] = make_uint2(pack2(l0, l1), pack2(l2, l3));
}

__global__ __launch_bounds__(256) void conv_bc(const float* __restrict__ A,
                                               const float* __restrict__ Wg) {
    int i = blockIdx.x * 256 + threadIdx.x;   // 1024*160
    if (i >= 160 * 1024) return;
    int d = i / 160, j = i % 160;
    float v = 0.f;
    if (j < 128) { int e = j >> 4, r = j & 15; v = A[(size_t)e * 16384 + d * 16 + r]; }
    else if (j < 136) v = Wg[(size_t)d * 8 + (j - 128)];
    __nv_bfloat16 h, l; split2(v, h, l);
    g_Bc_h[i] = h; g_Bc_l[i] = l;
}

__global__ __launch_bounds__(256) void conv_bf(const float4* __restrict__ B) {
    int i = blockIdx.x * 256 + threadIdx.x;   // 32K float4
    float4 v = B[i];
    __nv_bfloat16 h0, h1, h2, h3, l0, l1, l2, l3;
    split2(v.x, h0, l0); split2(v.y, h1, l1);
    split2(v.z, h2, l2); split2(v.w, h3, l3);
    ((uint2*)g_Bf_h)[i] = make_uint2(pack2(h0, h1), pack2(h2, h3));
    ((uint2*)g_Bf_l)[i] = make_uint2(pack2(l0, l1), pack2(l2, l3));
}

// ---------------- Router: top-2 softmax + dense gated H ----------------
__global__ __launch_bounds__(256) void router_k(float* __restrict__ out_logits,
                                                float* __restrict__ out_sel,
                                                float* __restrict__ out_wts) {
    int w = threadIdx.x >> 5, lane = threadIdx.x & 31;
    int n = blockIdx.x * 8 + w;
    const float* hrow = g_h + (size_t)n * 160;
    float lg = (lane < 8) ? hrow[128 + lane] : -1e30f;
    if (lane < 8) out_logits[(size_t)n * 8 + lane] = lg;
    float v0 = -1e30f; int i0 = 0;
    #pragma unroll
    for (int e = 0; e < 8; e++) {
        float v = __shfl_sync(0xffffffffu, lg, e);
        if (v > v0) { v0 = v; i0 = e; }
    }
    float v1 = -1e30f; int i1 = 0;
    #pragma unroll
    for (int e = 0; e < 8; e++) {
        float v = __shfl_sync(0xffffffffu, lg, e);
        if (e != i0 && v > v1) { v1 = v; i1 = e; }
    }
    float e1v = __expf(v1 - v0);
    float p0 = 1.0f / (1.0f + e1v);
    float p1 = e1v * p0;
    if (lane == 0) {
        out_sel[(size_t)n * 2 + 0] = (float)i0;
        out_sel[(size_t)n * 2 + 1] = (float)i1;
        out_wts[(size_t)n * 2 + 0] = p0;
        out_wts[(size_t)n * 2 + 1] = p1;
    }
    float s0 = SCALING * p0, s1 = SCALING * p1;
    int j0 = lane * 4;
    int e = lane >> 2;
    float g = (e == i0) ? s0 : ((e == i1) ? s1 : 0.f);
    float4 h4 = *(const float4*)(hrow + j0);
    __nv_bfloat16 h0, h1, h2, h3, l0, l1, l2, l3;
    split2(h4.x * g, h0, l0); split2(h4.y * g, h1, l1);
    split2(h4.z * g, h2, l2); split2(h4.w * g, h3, l3);
    *(uint2*)&g_Hh[(size_t)n * 128 + j0] = make_uint2(pack2(h0, h1), pack2(h2, h3));
    *(uint2*)&g_Hl[(size_t)n * 128 + j0] = make_uint2(pack2(l0, l1), pack2(l2, l3));
}

// ---------------- HMMA split-bf16 GEMM, 4-stage cp.async ----------------
// BM=128, BK=32, 8 warps as 4(m) x 2(n); warp tile 32 x (BN/2).
// WHICH=0: g_h = tokens @ Bc         (BN=160, K=3x1024)
// WHICH=1: out = tokens @ W + H @ Bf (BN=128, K=3x1024 + 3x128)
template<int BN, int WHICH>
__global__ __launch_bounds__(256, 2) void gemm_mma(float* __restrict__ outp) {
    constexpr int BM = 128, BK = 32, NST = 4;
    constexpr int HN = BN / 2;
    constexpr int N8 = HN / 8;
    constexpr int NT2 = N8 / 2;
    constexpr int LDA = BK + 8;
    constexpr int LDB = BN + 8;
    constexpr uint32_t ASZ = BM * LDA * 2, BSZ = BK * LDB * 2;
    constexpr uint32_t STG = ASZ + BSZ;

    extern __shared__ __align__(16) char smem[];
    const uint32_t sA = s2u(smem);            // per stage: [A | B]
    const uint32_t sB = sA + ASZ;

    const int tid = threadIdx.x, w = tid >> 5, lane = tid & 31;
    const int wm = w & 3, wn = w >> 2;
    const int lr = lane & 15, lc8 = (lane >> 4) * 8;
    const int bm = blockIdx.y * BM;
    const int bn = blockIdx.x * BN;

    // K-segment tables
    const __nv_bfloat16 *Asrc[6], *Bsrc[6];
    int astr[6], kst[7];
    int NSEG, TOT;
    if constexpr (WHICH == 0) {
        Asrc[0] = g_Ah; Asrc[1] = g_Ah; Asrc[2] = g_Al;
        Bsrc[0] = g_Bc_h; Bsrc[1] = g_Bc_l; Bsrc[2] = g_Bc_h;
        astr[0] = astr[1] = astr[2] = 1024;
        kst[0] = 0; kst[1] = 1024; kst[2] = 2048; kst[3] = 3072;
        NSEG = 3; TOT = 3072 / BK;
    } else {
        Asrc[0] = g_Ah; Asrc[1] = g_Ah; Asrc[2] = g_Al;
        Bsrc[0] = g_Wh; Bsrc[1] = g_Wl; Bsrc[2] = g_Wh;
        Asrc[3] = g_Hh; Asrc[4] = g_Hh; Asrc[5] = g_Hl;
        Bsrc[3] = g_Bf_h; Bsrc[4] = g_Bf_l; Bsrc[5] = g_Bf_h;
        astr[0] = astr[1] = astr[2] = 1024;
        astr[3] = astr[4] = astr[5] = 128;
        kst[0] = 0; kst[1] = 1024; kst[2] = 2048; kst[3] = 3072;
        kst[4] = 3200; kst[5] = 3328; kst[6] = 3456;
        NSEG = 6; TOT = 3456 / BK;
    }
    const int bstr = (WHICH == 0) ? 160 : 1024;

    auto load_tile = [&](int t, int buf) {
        int kg = t * BK, si = 0;
        while (si < NSEG - 1 && kg >= kst[si + 1]) si++;
        const __nv_bfloat16* Ap = Asrc[si] + (size_t)bm * astr[si] + (kg - kst[si]);
        const __nv_bfloat16* Bp = Bsrc[si] + (size_t)(kg - kst[si]) * bstr + bn;
        const int as = astr[si];
        const uint32_t dA = sA + buf * STG, dB = sB + buf * STG;
        #pragma unroll
        for (int i = 0; i < 2; i++) {                       // A: 128 x 32 halves
            int idx = tid + i * 256;
            int row = idx >> 2, c = idx & 3;
            cp16(dA + (row * LDA + c * 8) * 2, Ap + (size_t)row * as + c * 8);
        }
        constexpr int NBCH = BK * BN / 8;                   // B: 32 x BN halves
        #pragma unroll
        for (int i = 0; i < (NBCH + 255) / 256; i++) {
            int idx = tid + i * 256;
            if ((NBCH % 256 == 0) || idx < NBCH) {
                int row = idx / (BN / 8), c = idx % (BN / 8);
                cp16(dB + (row * LDB + c * 8) * 2, Bp + (size_t)row * bstr + c * 8);
            }
        }
    };

    float acc[2][N8][4];
    #pragma unroll
    for (int mt = 0; mt < 2; mt++)
        #pragma unroll
        for (int nt = 0; nt < N8; nt++)
            #pragma unroll
            for (int q = 0; q < 4; q++) acc[mt][nt][q] = 0.f;

    uint32_t aab[2], bab[NT2];
    #pragma unroll
    for (int mt = 0; mt < 2; mt++)
        aab[mt] = sA + ((wm * 32 + mt * 16 + lr) * LDA + lc8) * 2;
    #pragma unroll
    for (int nt2 = 0; nt2 < NT2; nt2++)
        bab[nt2] = sB + (lr * LDB + wn * HN + nt2 * 16 + lc8) * 2;

    // prologue: fill 3 stages
    #pragma unroll
    for (int p = 0; p < NST - 1; p++) { load_tile(p, p); CP_COMMIT(); }

    for (int t = 0; t < TOT; t++) {
        const int buf = t & (NST - 1);
        asm volatile("cp.async.wait_group %0;" :: "n"(NST - 2));
        __syncthreads();
        // prefetch stage t+3 into buffer consumed at iter t-1
        if (t + NST - 1 < TOT) load_tile(t + NST - 1, (t + NST - 1) & (NST - 1));
        CP_COMMIT();

        const uint32_t aoff = buf * STG, boff = buf * STG;
        #pragma unroll
        for (int kk = 0; kk < BK; kk += 16) {
            uint32_t af[2][4];
            ldsm4(af[0], aab[0] + aoff + kk * 2);
            ldsm4(af[1], aab[1] + aoff + kk * 2);
            #pragma unroll
            for (int nt2 = 0; nt2 < NT2; nt2++) {
                uint32_t bf[4];
                ldsm4t(bf, bab[nt2] + boff + kk * LDB * 2);
                #pragma unroll
                for (int mt = 0; mt < 2; mt++) {
                    mma_bf16(acc[mt][2 * nt2],     af[mt], bf[0], bf[1]);
                    mma_bf16(acc[mt][2 * nt2 + 1], af[mt], bf[2], bf[3]);
                }
            }
        }
    }

    // epilogue
    float* out = (WHICH == 0) ? g_h : outp;
    const int ld = (WHICH == 0) ? 160 : D_OUT;
    #pragma unroll
    for (int mt = 0; mt < 2; mt++) {
        int r0 = bm + wm * 32 + mt * 16 + (lane >> 2);
        #pragma unroll
        for (int nt = 0; nt < N8; nt++) {
            int c0 = bn + wn * HN + nt * 8 + 2 * (lane & 3);
            *(float2*)(out + (size_t)r0 * ld + c0) =
                make_float2(acc[mt][nt][0], acc[mt][nt][1]);
            *(float2*)(out + (size_t)(r0 + 8) * ld + c0) =
                make_float2(acc[mt][nt][2], acc[mt][nt][3]);
        }
    }
}

// ---------------- Launch ----------------
extern "C" void kernel_launch(void* const* d_in, const int* in_sizes, int n_in,
                              void* d_out, int out_size) {
    const float* tokens = (const float*)d_in[0];
    const float* W_base = (const float*)d_in[1];
    const float* A      = (const float*)d_in[2];
    const float* B      = (const float*)d_in[3];
    const float* W_gate = (const float*)d_in[4];

    float* out        = (float*)d_out;
    float* out_logits = out + (size_t)N_TOK * D_OUT;
    float* out_sel    = out_logits + (size_t)N_TOK * N_EXP;
    float* out_wts    = out_sel + (size_t)N_TOK * 2;

    // dynamic smem sizes: 4 stages x (A + B)
    const int smem1 = 4 * (128 * 40 + 32 * 168) * 2;   // BN=160 : 53,504 B... computed below
    const int smem2 = 4 * (128 * 40 + 32 * 136) * 2;   // BN=128
    // (A stage = 128*(32+8) halves; B stage = 32*(BN+8) halves)

    cudaFuncSetAttribute(gemm_mma<160, 0>,
                         cudaFuncAttributeMaxDynamicSharedMemorySize, smem1);
    cudaFuncSetAttribute(gemm_mma<128, 1>,
                         cudaFuncAttributeMaxDynamicSharedMemorySize, smem2);

    conv_tok<<<16384, 256>>>((const float4*)tokens);
    conv_w<<<1024, 256>>>((const float4*)W_base);
    conv_bc<<<640, 256>>>(A, W_gate);
    conv_bf<<<128, 256>>>((const float4*)B);

    gemm_mma<160, 0><<<dim3(1, N_TOK / 128), 256, smem1>>>(nullptr);

    router_k<<<N_TOK / 8, 256>>>(out_logits, out_sel, out_wts);

    gemm_mma<128, 1><<<dim3(D_OUT / 128, N_TOK / 128), 256, smem2>>>(out);
}